// round 15
// baseline (speedup 1.0000x reference)
#include <cuda_runtime.h>
#include <cstdint>

// ---------------------------------------------------------------------------
// Problem constants
// ---------------------------------------------------------------------------
#define T0 4096
#define T1 8192
#define BATCH 8
#define KSZ 15
#define PADSZ 7
#define NJ 27
#define NEDGE 157

// Scratch (device globals; allocation is forbidden)
__device__ float g_bufA[BATCH * 270 * T1];
__device__ float g_bufB[BATCH * 270 * T1];
__device__ float g_bufC[BATCH * 162 * T1];      // pre-summed input (x + noise)
__device__ float g_gi[BATCH * 162 * T1];
__device__ __align__(16) float g_wpad[1205760]; // padded edge-major weights

// ---------------------------------------------------------------------------
// Skeleton adjacency
// ---------------------------------------------------------------------------
__constant__ int c_nb_cnt[NJ] = {
    8, 7, 6, 5, 4, 7, 6, 5, 4, 7, 8, 9, 6, 3, 7, 5, 4, 3, 7, 5, 4, 3, 6, 5, 6, 5, 12
};
__constant__ int c_nb_off[NJ] = {
    0, 8, 15, 21, 26, 30, 37, 43, 48, 52, 59, 67, 76, 82, 85, 92, 97, 101,
    104, 111, 116, 120, 123, 129, 134, 140, 145
};
__constant__ unsigned char c_edge_j[NEDGE] = {
    0,0,0,0,0,0,0,0, 1,1,1,1,1,1,1, 2,2,2,2,2,2, 3,3,3,3,3, 4,4,4,4,
    5,5,5,5,5,5,5, 6,6,6,6,6,6, 7,7,7,7,7, 8,8,8,8, 9,9,9,9,9,9,9,
    10,10,10,10,10,10,10,10, 11,11,11,11,11,11,11,11,11, 12,12,12,12,12,12,
    13,13,13, 14,14,14,14,14,14,14, 15,15,15,15,15, 16,16,16,16, 17,17,17,
    18,18,18,18,18,18,18, 19,19,19,19,19, 20,20,20,20, 21,21,21,
    22,22,22,22,22,22, 23,23,23,23,23, 24,24,24,24,24,24, 25,25,25,25,25,
    26,26,26,26,26,26,26,26,26,26,26,26
};
__constant__ unsigned char c_edge_jn[NEDGE] = {
    0,1,2,5,6,9,10,26, 0,1,2,3,5,9,26, 0,1,2,3,4,26, 1,2,3,4,22, 2,3,4,23,
    0,1,5,6,7,9,26, 0,5,6,7,8,26, 5,6,7,8,24, 6,7,8,25, 0,1,5,9,10,11,26,
    0,9,10,11,12,14,18,26, 9,10,11,12,13,14,15,18,19, 10,11,12,13,14,18,
    11,12,13, 10,11,12,14,15,16,18, 11,14,15,16,17, 14,15,16,17, 15,16,17,
    10,11,12,14,18,19,20, 11,18,19,20,21, 18,19,20,21, 19,20,21,
    1,2,3,4,22,26, 2,3,4,23,26, 5,6,7,8,24,26, 6,7,8,25,26,
    0,1,2,5,6,9,10,22,23,24,25,26
};
__constant__ int c_nb[NJ][12] = {
    {0,1,2,5,6,9,10,26,0,0,0,0}, {0,1,2,3,5,9,26,0,0,0,0,0},
    {0,1,2,3,4,26,0,0,0,0,0,0}, {1,2,3,4,22,0,0,0,0,0,0,0},
    {2,3,4,23,0,0,0,0,0,0,0,0}, {0,1,5,6,7,9,26,0,0,0,0,0},
    {0,5,6,7,8,26,0,0,0,0,0,0}, {5,6,7,8,24,0,0,0,0,0,0,0},
    {6,7,8,25,0,0,0,0,0,0,0,0}, {0,1,5,9,10,11,26,0,0,0,0,0},
    {0,9,10,11,12,14,18,26,0,0,0,0}, {9,10,11,12,13,14,15,18,19,0,0,0},
    {10,11,12,13,14,18,0,0,0,0,0,0}, {11,12,13,0,0,0,0,0,0,0,0,0},
    {10,11,12,14,15,16,18,0,0,0,0,0}, {11,14,15,16,17,0,0,0,0,0,0,0},
    {14,15,16,17,0,0,0,0,0,0,0,0}, {15,16,17,0,0,0,0,0,0,0,0,0},
    {10,11,12,14,18,19,20,0,0,0,0,0}, {11,18,19,20,21,0,0,0,0,0,0,0},
    {18,19,20,21,0,0,0,0,0,0,0,0}, {19,20,21,0,0,0,0,0,0,0,0,0},
    {1,2,3,4,22,26,0,0,0,0,0,0}, {2,3,4,23,26,0,0,0,0,0,0,0},
    {5,6,7,8,24,26,0,0,0,0,0,0}, {6,7,8,25,26,0,0,0,0,0,0,0},
    {0,1,2,5,6,9,10,22,23,24,25,26}
};

// ---------------------------------------------------------------------------
// cp.async helpers
// ---------------------------------------------------------------------------
__device__ __forceinline__ void cp4(float* dst_smem, const float* src) {
    uint32_t d = (uint32_t)__cvta_generic_to_shared(dst_smem);
    asm volatile("cp.async.ca.shared.global [%0], [%1], 4;" :: "r"(d), "l"(src));
}
__device__ __forceinline__ void cp16(float* dst_smem, const float* src) {
    uint32_t d = (uint32_t)__cvta_generic_to_shared(dst_smem);
    asm volatile("cp.async.cg.shared.global [%0], [%1], 16;" :: "r"(d), "l"(src));
}
__device__ __forceinline__ void cp_commit() {
    asm volatile("cp.async.commit_group;" ::: "memory");
}
template <int N>
__device__ __forceinline__ void cp_wait() {
    asm volatile("cp.async.wait_group %0;" :: "n"(N) : "memory");
}

// ---------------------------------------------------------------------------
// Single weight pre-pack kernel for all 8 layers.
//   wpad[((e*CO + co)*CI + ci)*16 + k], slot 15 = 0
// ---------------------------------------------------------------------------
__global__ void pack_all_kernel(const float* w0, const float* w1, const float* w2,
                                const float* w3, const float* w4, const float* w5,
                                const float* w6, const float* w7,
                                float* __restrict__ wpad)
{
    int idx = blockIdx.x * blockDim.x + threadIdx.x;
    if (idx >= 1205760) return;
    int s = (idx >= 602880) ? 1 : 0;
    int r = idx - s * 602880;
    int l, ci_pj, co_pj, base;
    if (r < 75360)       { l = 0; ci_pj = 6;  co_pj = 5;  base = 0; }
    else if (r < 200960) { l = 1; ci_pj = 5;  co_pj = 10; base = 75360; }
    else if (r < 452160) { l = 2; ci_pj = 10; co_pj = 10; base = 200960; }
    else                 { l = 3; ci_pj = 10; co_pj = 6;  base = 452160; }
    const float* wsrc;
    {
        const float* tbl[8] = {w0, w1, w2, w3, w4, w5, w6, w7};
        wsrc = tbl[s * 4 + l];
    }
    int q = r - base;
    int k = q & 15;
    int t = q >> 4;
    int ci = t % ci_pj;  t /= ci_pj;
    int co = t % co_pj;
    int e  = t / co_pj;
    int j  = c_edge_j[e];
    int jn = c_edge_jn[e];
    float v = 0.0f;
    if (k < KSZ)
        v = wsrc[((size_t)(j * co_pj + co) * (ci_pj * NJ) + jn * ci_pj + ci) * KSZ + k];
    wpad[idx] = v;
}

// ===========================================================================
// Variant A: 1 output channel/thread, TT=512 / TPT=16 (time amortization).
//   grid = (T/512, 27, BATCH), block = (32, CO_PJ)
//   smem x row holds [t0-8, t0+504+24) -> logical p in [0,528), xv idx tt+k+1
// ===========================================================================
template <int CI_PJ, int CO_PJ, bool ADD_RES, bool LRELU, int MINBLK>
__global__ void __launch_bounds__(32 * CO_PJ, MINBLK)
sconv1_kernel(const float* __restrict__ x,
              const float* __restrict__ wpad,
              const float* __restrict__ bias,
              const float* __restrict__ res,
              float* __restrict__ y,
              int T)
{
    constexpr int CIN   = CI_PJ * NJ;
    constexpr int COUT  = CO_PJ * NJ;
    constexpr int TT    = 512;
    constexpr int TPT   = 16;
    constexpr int LROW  = 528;                  // floats per logical row
    constexpr int PROW  = 592;                  // pad-4-per-32 physical row
    constexpr int NT    = 32 * CO_PJ;
    constexpr int NCH   = LROW / 4;             // 132 16B chunks per row
    constexpr int XFL   = CI_PJ * PROW;
    constexpr int WFL   = CO_PJ * CI_PJ * 16;

    extern __shared__ __align__(16) float smf[];
    float* swb = smf + 2 * XFL;

    const int b   = blockIdx.z;
    const int j   = blockIdx.y;
    const int t0  = blockIdx.x * TT;
    const int tx  = threadIdx.x;
    const int col = threadIdx.y;
    const int tid = col * 32 + tx;
    const int t_local = tx * TPT;
    const bool boundary = (blockIdx.x == 0) | (blockIdx.x == gridDim.x - 1);

    float acc[TPT];
#pragma unroll
    for (int i = 0; i < TPT; ++i) acc[i] = 0.0f;

    const int cnt  = c_nb_cnt[j];
    const int eoff = c_nb_off[j];

    auto stage = [&](int bb, int ji) {
        const int jn = c_nb[j][ji];
        float* sx = smf + bb * XFL;
        const float* xb_ = x + ((size_t)b * CIN + jn * CI_PJ) * (size_t)T + t0 - 8;
        if (!boundary) {
            for (int ci = col; ci < CI_PJ; ci += CO_PJ) {
                const float* src = xb_ + (size_t)ci * T;
                float* drow = sx + ci * PROW;
#pragma unroll
                for (int c0 = 0; c0 < NCH; c0 += 32) {
                    int c = c0 + tx;
                    if (c0 + 32 <= NCH || c < NCH)
                        cp16(drow + 4 * c + 4 * (c >> 3), src + 4 * c);
                }
            }
        } else {
            for (int ci = col; ci < CI_PJ; ci += CO_PJ) {
                const float* src = xb_ + (size_t)ci * T;
                float* drow = sx + ci * PROW;
#pragma unroll
                for (int s = 0; s < (LROW + 31) / 32; ++s) {
                    int p = tx + 32 * s;
                    if (p < LROW) {
                        int g = t0 - 8 + p;
                        g = (g < 0) ? -g : (g >= T ? 2 * T - 2 - g : g);
                        cp4(drow + p + 4 * (p >> 5), src + (g - (t0 - 8)));
                    }
                }
            }
        }
        const float* wsrc = wpad + (size_t)(eoff + ji) * WFL;
        float* sw = swb + bb * WFL;
        for (int i = tid; i < WFL / 4; i += NT)
            cp16(sw + 4 * i, wsrc + 4 * i);
    };

    auto compute = [&](int bb) {
        const float* sx = smf + bb * XFL;
        const float* swp = swb + bb * WFL + col * CI_PJ * 16;
#pragma unroll
        for (int ci = 0; ci < CI_PJ; ++ci) {
            float xv[32];                        // tt+k+1 max = 15+15+1 = 31
            {
                const float* xrow = &sx[ci * PROW];
#pragma unroll
                for (int c = 0; c < 8; ++c) {
                    int lg = t_local + 4 * c;
                    int ph = lg + 4 * (lg >> 5);
                    ((float4*)xv)[c] = *(const float4*)(xrow + ph);
                }
            }
#pragma unroll
            for (int kc = 0; kc < 4; ++kc) {
                float4 w4 = *(const float4*)(swp + ci * 16 + 4 * kc);
                const float wa[4] = {w4.x, w4.y, w4.z, w4.w};
#pragma unroll
                for (int kk = 0; kk < 4; ++kk) {
                    const int k = 4 * kc + kk;   // k = 15 has zero weight
#pragma unroll
                    for (int tt = 0; tt < TPT; ++tt)
                        acc[tt] = fmaf(wa[kk], xv[tt + k + 1], acc[tt]);
                }
            }
        }
    };

    stage(0, 0);
    cp_commit();
    int buf = 0;
    for (int ji = 0; ji < cnt; ++ji) {
        __syncthreads();
        if (ji + 1 < cnt) {
            stage(buf ^ 1, ji + 1);
            cp_commit();
            cp_wait<1>();
        } else {
            cp_wait<0>();
        }
        __syncthreads();
        compute(buf);
        buf ^= 1;
    }

    const int cg = j * CO_PJ + col;
    const float bv = bias[cg];
    float outv[TPT];
#pragma unroll
    for (int tt = 0; tt < TPT; ++tt) {
        float v = acc[tt] + bv;
        if (LRELU) v = (v > 0.0f) ? v : 0.2f * v;
        outv[tt] = v;
    }
    const size_t obase = ((size_t)b * COUT + cg) * (size_t)T + t0 + t_local;
    if (ADD_RES) {
#pragma unroll
        for (int q = 0; q < 4; ++q) {
            float4 r4 = *(const float4*)(res + obase + 4 * q);
            outv[4 * q + 0] += r4.x; outv[4 * q + 1] += r4.y;
            outv[4 * q + 2] += r4.z; outv[4 * q + 3] += r4.w;
        }
    }
#pragma unroll
    for (int q = 0; q < 4; ++q)
        *(float4*)(y + obase + 4 * q) =
            make_float4(outv[4 * q], outv[4 * q + 1], outv[4 * q + 2], outv[4 * q + 3]);
}

// ===========================================================================
// Variant B: 2 output channels/thread, TT=256 / TPT=8 (R12 exact).
//   grid = (T/256, 27, BATCH), block = (32, CO_PJ/2)
// ===========================================================================
template <int CI_PJ, int CO_PJ, bool ADD_RES, bool LRELU, int MINBLK>
__global__ void __launch_bounds__(32 * (CO_PJ / 2), MINBLK)
sconv2_kernel(const float* __restrict__ x,
              const float* __restrict__ wpad,
              const float* __restrict__ bias,
              const float* __restrict__ res,
              float* __restrict__ y,
              int T)
{
    static_assert(CO_PJ % 2 == 0, "variant B requires even CO_PJ");
    constexpr int CIN   = CI_PJ * NJ;
    constexpr int COUT  = CO_PJ * NJ;
    constexpr int NPAIR = CO_PJ / 2;
    constexpr int TT    = 256;
    constexpr int TPT   = 8;
    constexpr int LROW  = 272;
    constexpr int PROW  = 304;
    constexpr int NT    = 32 * NPAIR;
    constexpr int NCH   = LROW / 4;
    constexpr int XFL   = CI_PJ * PROW;
    constexpr int WFL   = CO_PJ * CI_PJ * 16;

    extern __shared__ __align__(16) float smf[];
    float* swb = smf + 2 * XFL;

    const int b   = blockIdx.z;
    const int j   = blockIdx.y;
    const int t0  = blockIdx.x * TT;
    const int tx  = threadIdx.x;
    const int pr  = threadIdx.y;
    const int tid = pr * 32 + tx;
    const int t_local = tx * TPT;
    const int co0 = 2 * pr;
    const bool boundary = (blockIdx.x == 0) | (blockIdx.x == gridDim.x - 1);

    float acc0[TPT], acc1[TPT];
#pragma unroll
    for (int i = 0; i < TPT; ++i) { acc0[i] = 0.0f; acc1[i] = 0.0f; }

    const int cnt  = c_nb_cnt[j];
    const int eoff = c_nb_off[j];

    auto stage = [&](int bb, int ji) {
        const int jn = c_nb[j][ji];
        float* sx = smf + bb * XFL;
        const float* xb_ = x + ((size_t)b * CIN + jn * CI_PJ) * (size_t)T + t0 - 8;
        if (!boundary) {
            for (int ci = pr; ci < CI_PJ; ci += NPAIR) {
                const float* src = xb_ + (size_t)ci * T;
                float* drow = sx + ci * PROW;
#pragma unroll
                for (int c0 = 0; c0 < NCH; c0 += 32) {
                    int c = c0 + tx;
                    if (c0 + 32 <= NCH || c < NCH)
                        cp16(drow + 4 * c + 4 * (c >> 3), src + 4 * c);
                }
            }
        } else {
            for (int ci = pr; ci < CI_PJ; ci += NPAIR) {
                const float* src = xb_ + (size_t)ci * T;
                float* drow = sx + ci * PROW;
#pragma unroll
                for (int s = 0; s < (LROW + 31) / 32; ++s) {
                    int p = tx + 32 * s;
                    if (p < LROW) {
                        int g = t0 - 8 + p;
                        g = (g < 0) ? -g : (g >= T ? 2 * T - 2 - g : g);
                        cp4(drow + p + 4 * (p >> 5), src + (g - (t0 - 8)));
                    }
                }
            }
        }
        const float* wsrc = wpad + (size_t)(eoff + ji) * WFL;
        float* sw = swb + bb * WFL;
        for (int i = tid; i < WFL / 4; i += NT)
            cp16(sw + 4 * i, wsrc + 4 * i);
    };

    auto compute = [&](int bb) {
        const float* sx = smf + bb * XFL;
        const float* swp0 = swb + bb * WFL + co0 * CI_PJ * 16;
        const float* swp1 = swp0 + CI_PJ * 16;
#pragma unroll
        for (int ci = 0; ci < CI_PJ; ++ci) {
            float xv[24];
            {
                const float* xrow = &sx[ci * PROW];
#pragma unroll
                for (int c = 0; c < 6; ++c) {
                    int lg = t_local + 4 * c;
                    int ph = lg + 4 * (lg >> 5);
                    ((float4*)xv)[c] = *(const float4*)(xrow + ph);
                }
            }
#pragma unroll
            for (int kc = 0; kc < 4; ++kc) {
                float4 w0 = *(const float4*)(swp0 + ci * 16 + 4 * kc);
                float4 w1 = *(const float4*)(swp1 + ci * 16 + 4 * kc);
                const float wa[4] = {w0.x, w0.y, w0.z, w0.w};
                const float wb[4] = {w1.x, w1.y, w1.z, w1.w};
#pragma unroll
                for (int kk = 0; kk < 4; ++kk) {
                    const int k = 4 * kc + kk;
#pragma unroll
                    for (int tt = 0; tt < TPT; ++tt) {
                        acc0[tt] = fmaf(wa[kk], xv[tt + k + 1], acc0[tt]);
                        acc1[tt] = fmaf(wb[kk], xv[tt + k + 1], acc1[tt]);
                    }
                }
            }
        }
    };

    stage(0, 0);
    cp_commit();
    int buf = 0;
    for (int ji = 0; ji < cnt; ++ji) {
        __syncthreads();
        if (ji + 1 < cnt) {
            stage(buf ^ 1, ji + 1);
            cp_commit();
            cp_wait<1>();
        } else {
            cp_wait<0>();
        }
        __syncthreads();
        compute(buf);
        buf ^= 1;
    }

    const int cg0 = j * CO_PJ + co0;
    const float bv0 = bias[cg0];
    const float bv1 = bias[cg0 + 1];

    float o0[TPT], o1[TPT];
#pragma unroll
    for (int tt = 0; tt < TPT; ++tt) {
        float v0 = acc0[tt] + bv0;
        float v1 = acc1[tt] + bv1;
        if (LRELU) {
            v0 = (v0 > 0.0f) ? v0 : 0.2f * v0;
            v1 = (v1 > 0.0f) ? v1 : 0.2f * v1;
        }
        o0[tt] = v0;  o1[tt] = v1;
    }
    const size_t base0 = ((size_t)b * COUT + cg0) * (size_t)T + t0 + t_local;
    if (ADD_RES) {
#pragma unroll
        for (int q = 0; q < 2; ++q) {
            float4 r4 = *(const float4*)(res + base0 + 4 * q);
            o0[4 * q + 0] += r4.x; o0[4 * q + 1] += r4.y;
            o0[4 * q + 2] += r4.z; o0[4 * q + 3] += r4.w;
        }
#pragma unroll
        for (int q = 0; q < 2; ++q) {
            float4 r4 = *(const float4*)(res + base0 + (size_t)T + 4 * q);
            o1[4 * q + 0] += r4.x; o1[4 * q + 1] += r4.y;
            o1[4 * q + 2] += r4.z; o1[4 * q + 3] += r4.w;
        }
    }
#pragma unroll
    for (int q = 0; q < 2; ++q)
        *(float4*)(y + base0 + 4 * q) =
            make_float4(o0[4 * q], o0[4 * q + 1], o0[4 * q + 2], o0[4 * q + 3]);
#pragma unroll
    for (int q = 0; q < 2; ++q)
        *(float4*)(y + base0 + (size_t)T + 4 * q) =
            make_float4(o1[4 * q], o1[4 * q + 1], o1[4 * q + 2], o1[4 * q + 3]);
}

// ---------------------------------------------------------------------------
// Elementwise sum
// ---------------------------------------------------------------------------
__global__ void add_kernel(const float* __restrict__ a, const float* __restrict__ bsrc,
                           float* __restrict__ out, int n)
{
    int i = blockIdx.x * blockDim.x + threadIdx.x;
    int i4 = 4 * i;
    if (i4 + 3 < n) {
        float4 va = *(const float4*)(a + i4);
        float4 vb = *(const float4*)(bsrc + i4);
        *(float4*)(out + i4) = make_float4(va.x + vb.x, va.y + vb.y,
                                           va.z + vb.z, va.w + vb.w);
    }
}

// ---------------------------------------------------------------------------
// Linear interp (align_corners=False) fused with noise add
// ---------------------------------------------------------------------------
__global__ void interp_add_kernel(const float* __restrict__ in,
                                  const float* __restrict__ noise,
                                  float* __restrict__ gi,
                                  float* __restrict__ sum,
                                  int Tin, int Tout, int BC)
{
    int idx = blockIdx.x * blockDim.x + threadIdx.x;
    if (idx >= BC * Tout) return;
    int t  = idx % Tout;
    int bc = idx / Tout;
    float src = ((float)t + 0.5f) * ((float)Tin / (float)Tout) - 0.5f;
    src = fminf(fmaxf(src, 0.0f), (float)(Tin - 1));
    int i0 = (int)floorf(src);
    int i1 = min(i0 + 1, Tin - 1);
    float wgt = src - (float)i0;
    const float* row = in + (size_t)bc * Tin;
    float v = row[i0] * (1.0f - wgt) + row[i1] * wgt;
    gi[idx]  = v;
    sum[idx] = v + noise[idx];
}

// ---------------------------------------------------------------------------
// Launch
// ---------------------------------------------------------------------------
static inline size_t smem_bytes1(int ci_pj, int co_pj) {   // variant A (TT=512)
    return 2u * ((size_t)ci_pj * 592 + (size_t)co_pj * ci_pj * 16) * 4u;
}
static inline size_t smem_bytes2(int ci_pj, int co_pj) {   // variant B (TT=256)
    return 2u * ((size_t)ci_pj * 304 + (size_t)co_pj * ci_pj * 16) * 4u;
}

extern "C" void kernel_launch(void* const* d_in, const int* in_sizes, int n_in,
                              void* d_out, int out_size)
{
    (void)in_sizes; (void)n_in; (void)out_size;

    const float* noise0    = (const float*)d_in[0];
    const float* generated = (const float*)d_in[1];
    const float* noise1    = (const float*)d_in[2];

    const float* W[2][4];
    const float* Bv[2][4];
    int idx = 3;
    for (int s = 0; s < 2; ++s)
        for (int l = 0; l < 4; ++l) {
            W[s][l]  = (const float*)d_in[idx++];
            Bv[s][l] = (const float*)d_in[idx++];
        }

    float *bufA, *bufB, *bufC, *gi, *wpad;
    cudaGetSymbolAddress((void**)&bufA, g_bufA);
    cudaGetSymbolAddress((void**)&bufB, g_bufB);
    cudaGetSymbolAddress((void**)&bufC, g_bufC);
    cudaGetSymbolAddress((void**)&gi, g_gi);
    cudaGetSymbolAddress((void**)&wpad, g_wpad);

    float* g0 = (float*)d_out;
    float* g1 = g0 + (size_t)BATCH * 162 * T0;

    pack_all_kernel<<<(1205760 + 255) / 256, 256>>>(
        W[0][0], W[0][1], W[0][2], W[0][3],
        W[1][0], W[1][1], W[1][2], W[1][3], wpad);

    const size_t woff[2][4] = {
        {0, 75360, 200960, 452160},
        {602880, 602880 + 75360, 602880 + 200960, 602880 + 452160}
    };

    const size_t sm0 = smem_bytes1(6, 5);    // variant A, TT=512
    const size_t sm1 = smem_bytes2(5, 10);   // variant B
    const size_t sm2 = smem_bytes2(10, 10);  // variant B
    const size_t sm3 = smem_bytes1(10, 6);   // variant A, TT=512

    cudaFuncSetAttribute(sconv1_kernel<6, 5, false, true, 6>,
                         cudaFuncAttributeMaxDynamicSharedMemorySize, (int)sm0);
    cudaFuncSetAttribute(sconv2_kernel<5, 10, false, true, 6>,
                         cudaFuncAttributeMaxDynamicSharedMemorySize, (int)sm1);
    cudaFuncSetAttribute(sconv2_kernel<10, 10, false, true, 6>,
                         cudaFuncAttributeMaxDynamicSharedMemorySize, (int)sm2);
    cudaFuncSetAttribute(sconv1_kernel<10, 6, true, false, 4>,
                         cudaFuncAttributeMaxDynamicSharedMemorySize, (int)sm3);

    // ---------------- stage 0 (T = 4096) ----------------
    {
        int n0 = BATCH * 162 * T0;
        add_kernel<<<(n0 / 4 + 255) / 256, 256>>>(generated, noise0, bufC, n0);

        dim3 gridA(T0 / 512, NJ, BATCH);
        dim3 gridB(T0 / 256, NJ, BATCH);
        sconv1_kernel<6, 5, false, true, 6><<<gridA, dim3(32, 5), sm0>>>(
            bufC, wpad + woff[0][0], Bv[0][0], nullptr, bufA, T0);
        sconv2_kernel<5, 10, false, true, 6><<<gridB, dim3(32, 5), sm1>>>(
            bufA, wpad + woff[0][1], Bv[0][1], nullptr, bufB, T0);
        sconv2_kernel<10, 10, false, true, 6><<<gridB, dim3(32, 5), sm2>>>(
            bufB, wpad + woff[0][2], Bv[0][2], nullptr, bufA, T0);
        sconv1_kernel<10, 6, true, false, 4><<<gridA, dim3(32, 6), sm3>>>(
            bufA, wpad + woff[0][3], Bv[0][3], generated, g0, T0);
    }

    // ---------------- upsample + noise add ----------------
    {
        int n = BATCH * 162 * T1;
        interp_add_kernel<<<(n + 255) / 256, 256>>>(g0, noise1, gi, bufC,
                                                    T0, T1, BATCH * 162);
    }

    // ---------------- stage 1 (T = 8192) ----------------
    {
        dim3 gridA(T1 / 512, NJ, BATCH);
        dim3 gridB(T1 / 256, NJ, BATCH);
        sconv1_kernel<6, 5, false, true, 6><<<gridA, dim3(32, 5), sm0>>>(
            bufC, wpad + woff[1][0], Bv[1][0], nullptr, bufA, T1);
        sconv2_kernel<5, 10, false, true, 6><<<gridB, dim3(32, 5), sm1>>>(
            bufA, wpad + woff[1][1], Bv[1][1], nullptr, bufB, T1);
        sconv2_kernel<10, 10, false, true, 6><<<gridB, dim3(32, 5), sm2>>>(
            bufB, wpad + woff[1][2], Bv[1][2], nullptr, bufA, T1);
        sconv1_kernel<10, 6, true, false, 4><<<gridA, dim3(32, 6), sm3>>>(
            bufA, wpad + woff[1][3], Bv[1][3], gi, g1, T1);
    }
}

// round 16
// speedup vs baseline: 1.0194x; 1.0194x over previous
#include <cuda_runtime.h>
#include <cstdint>

// ---------------------------------------------------------------------------
// Problem constants
// ---------------------------------------------------------------------------
#define T0 4096
#define T1 8192
#define BATCH 8
#define KSZ 15
#define PADSZ 7
#define NJ 27
#define NEDGE 157

// Scratch (device globals; allocation is forbidden)
__device__ float g_bufA[BATCH * 270 * T1];
__device__ float g_bufB[BATCH * 270 * T1];
__device__ float g_bufC[BATCH * 162 * T1];      // pre-summed input (x + noise)
__device__ float g_gi[BATCH * 162 * T1];
__device__ __align__(16) float g_wpad[1205760]; // padded edge-major weights

// ---------------------------------------------------------------------------
// Skeleton adjacency
// ---------------------------------------------------------------------------
__constant__ int c_nb_cnt[NJ] = {
    8, 7, 6, 5, 4, 7, 6, 5, 4, 7, 8, 9, 6, 3, 7, 5, 4, 3, 7, 5, 4, 3, 6, 5, 6, 5, 12
};
__constant__ int c_nb_off[NJ] = {
    0, 8, 15, 21, 26, 30, 37, 43, 48, 52, 59, 67, 76, 82, 85, 92, 97, 101,
    104, 111, 116, 120, 123, 129, 134, 140, 145
};
__constant__ unsigned char c_edge_j[NEDGE] = {
    0,0,0,0,0,0,0,0, 1,1,1,1,1,1,1, 2,2,2,2,2,2, 3,3,3,3,3, 4,4,4,4,
    5,5,5,5,5,5,5, 6,6,6,6,6,6, 7,7,7,7,7, 8,8,8,8, 9,9,9,9,9,9,9,
    10,10,10,10,10,10,10,10, 11,11,11,11,11,11,11,11,11, 12,12,12,12,12,12,
    13,13,13, 14,14,14,14,14,14,14, 15,15,15,15,15, 16,16,16,16, 17,17,17,
    18,18,18,18,18,18,18, 19,19,19,19,19, 20,20,20,20, 21,21,21,
    22,22,22,22,22,22, 23,23,23,23,23, 24,24,24,24,24,24, 25,25,25,25,25,
    26,26,26,26,26,26,26,26,26,26,26,26
};
__constant__ unsigned char c_edge_jn[NEDGE] = {
    0,1,2,5,6,9,10,26, 0,1,2,3,5,9,26, 0,1,2,3,4,26, 1,2,3,4,22, 2,3,4,23,
    0,1,5,6,7,9,26, 0,5,6,7,8,26, 5,6,7,8,24, 6,7,8,25, 0,1,5,9,10,11,26,
    0,9,10,11,12,14,18,26, 9,10,11,12,13,14,15,18,19, 10,11,12,13,14,18,
    11,12,13, 10,11,12,14,15,16,18, 11,14,15,16,17, 14,15,16,17, 15,16,17,
    10,11,12,14,18,19,20, 11,18,19,20,21, 18,19,20,21, 19,20,21,
    1,2,3,4,22,26, 2,3,4,23,26, 5,6,7,8,24,26, 6,7,8,25,26,
    0,1,2,5,6,9,10,22,23,24,25,26
};
__constant__ int c_nb[NJ][12] = {
    {0,1,2,5,6,9,10,26,0,0,0,0}, {0,1,2,3,5,9,26,0,0,0,0,0},
    {0,1,2,3,4,26,0,0,0,0,0,0}, {1,2,3,4,22,0,0,0,0,0,0,0},
    {2,3,4,23,0,0,0,0,0,0,0,0}, {0,1,5,6,7,9,26,0,0,0,0,0},
    {0,5,6,7,8,26,0,0,0,0,0,0}, {5,6,7,8,24,0,0,0,0,0,0,0},
    {6,7,8,25,0,0,0,0,0,0,0,0}, {0,1,5,9,10,11,26,0,0,0,0,0},
    {0,9,10,11,12,14,18,26,0,0,0,0}, {9,10,11,12,13,14,15,18,19,0,0,0},
    {10,11,12,13,14,18,0,0,0,0,0,0}, {11,12,13,0,0,0,0,0,0,0,0,0},
    {10,11,12,14,15,16,18,0,0,0,0,0}, {11,14,15,16,17,0,0,0,0,0,0,0},
    {14,15,16,17,0,0,0,0,0,0,0,0}, {15,16,17,0,0,0,0,0,0,0,0,0},
    {10,11,12,14,18,19,20,0,0,0,0,0}, {11,18,19,20,21,0,0,0,0,0,0,0},
    {18,19,20,21,0,0,0,0,0,0,0,0}, {19,20,21,0,0,0,0,0,0,0,0,0},
    {1,2,3,4,22,26,0,0,0,0,0,0}, {2,3,4,23,26,0,0,0,0,0,0,0},
    {5,6,7,8,24,26,0,0,0,0,0,0}, {6,7,8,25,26,0,0,0,0,0,0,0},
    {0,1,2,5,6,9,10,22,23,24,25,26}
};

// ---------------------------------------------------------------------------
// cp.async helpers
// ---------------------------------------------------------------------------
__device__ __forceinline__ void cp4(float* dst_smem, const float* src) {
    uint32_t d = (uint32_t)__cvta_generic_to_shared(dst_smem);
    asm volatile("cp.async.ca.shared.global [%0], [%1], 4;" :: "r"(d), "l"(src));
}
__device__ __forceinline__ void cp16(float* dst_smem, const float* src) {
    uint32_t d = (uint32_t)__cvta_generic_to_shared(dst_smem);
    asm volatile("cp.async.cg.shared.global [%0], [%1], 16;" :: "r"(d), "l"(src));
}
__device__ __forceinline__ void cp_commit() {
    asm volatile("cp.async.commit_group;" ::: "memory");
}
template <int N>
__device__ __forceinline__ void cp_wait() {
    asm volatile("cp.async.wait_group %0;" :: "n"(N) : "memory");
}

// ---------------------------------------------------------------------------
// Single weight pre-pack kernel for all 8 layers.
//   wpad[((e*CO + co)*CI + ci)*16 + k], slot 15 = 0
// ---------------------------------------------------------------------------
__global__ void pack_all_kernel(const float* w0, const float* w1, const float* w2,
                                const float* w3, const float* w4, const float* w5,
                                const float* w6, const float* w7,
                                float* __restrict__ wpad)
{
    int idx = blockIdx.x * blockDim.x + threadIdx.x;
    if (idx >= 1205760) return;
    int s = (idx >= 602880) ? 1 : 0;
    int r = idx - s * 602880;
    int l, ci_pj, co_pj, base;
    if (r < 75360)       { l = 0; ci_pj = 6;  co_pj = 5;  base = 0; }
    else if (r < 200960) { l = 1; ci_pj = 5;  co_pj = 10; base = 75360; }
    else if (r < 452160) { l = 2; ci_pj = 10; co_pj = 10; base = 200960; }
    else                 { l = 3; ci_pj = 10; co_pj = 6;  base = 452160; }
    const float* wsrc;
    {
        const float* tbl[8] = {w0, w1, w2, w3, w4, w5, w6, w7};
        wsrc = tbl[s * 4 + l];
    }
    int q = r - base;
    int k = q & 15;
    int t = q >> 4;
    int ci = t % ci_pj;  t /= ci_pj;
    int co = t % co_pj;
    int e  = t / co_pj;
    int j  = c_edge_j[e];
    int jn = c_edge_jn[e];
    float v = 0.0f;
    if (k < KSZ)
        v = wsrc[((size_t)(j * co_pj + co) * (ci_pj * NJ) + jn * ci_pj + ci) * KSZ + k];
    wpad[idx] = v;
}

// ===========================================================================
// Variant A: 1 output channel/thread, TT=256/TPT=8 (R12 exact compute).
//   NBUF=2: two barriers/iter (double buffer).
//   NBUF=3: ONE barrier/iter (triple buffer; staging target is the buffer
//           last read 2 iterations ago -> safe after the single barrier).
//   grid = (T/256, 27, BATCH), block = (32, CO_PJ)
// ===========================================================================
template <int CI_PJ, int CO_PJ, bool ADD_RES, bool LRELU, int MINBLK, int NBUF>
__global__ void __launch_bounds__(32 * CO_PJ, MINBLK)
sconv1_kernel(const float* __restrict__ x,
              const float* __restrict__ wpad,
              const float* __restrict__ bias,
              const float* __restrict__ res,
              float* __restrict__ y,
              int T)
{
    constexpr int CIN   = CI_PJ * NJ;
    constexpr int COUT  = CO_PJ * NJ;
    constexpr int TT    = 256;
    constexpr int TPT   = 8;
    constexpr int LROW  = 272;
    constexpr int PROW  = 304;
    constexpr int NT    = 32 * CO_PJ;
    constexpr int NCH   = LROW / 4;
    constexpr int XFL   = CI_PJ * PROW;
    constexpr int WFL   = CO_PJ * CI_PJ * 16;

    extern __shared__ __align__(16) float smf[];
    float* swb = smf + NBUF * XFL;

    const int b   = blockIdx.z;
    const int j   = blockIdx.y;
    const int t0  = blockIdx.x * TT;
    const int tx  = threadIdx.x;
    const int col = threadIdx.y;
    const int tid = col * 32 + tx;
    const int t_local = tx * TPT;
    const bool boundary = (blockIdx.x == 0) | (blockIdx.x == gridDim.x - 1);

    float acc[TPT];
#pragma unroll
    for (int i = 0; i < TPT; ++i) acc[i] = 0.0f;

    const int cnt  = c_nb_cnt[j];
    const int eoff = c_nb_off[j];

    auto stage = [&](int bb, int ji) {
        const int jn = c_nb[j][ji];
        float* sx = smf + bb * XFL;
        const float* xb_ = x + ((size_t)b * CIN + jn * CI_PJ) * (size_t)T + t0 - 8;
        if (!boundary) {
            for (int ci = col; ci < CI_PJ; ci += CO_PJ) {
                const float* src = xb_ + (size_t)ci * T;
                float* drow = sx + ci * PROW;
#pragma unroll
                for (int c0 = 0; c0 < NCH; c0 += 32) {
                    int c = c0 + tx;
                    if (c0 + 32 <= NCH || c < NCH)
                        cp16(drow + 4 * c + 4 * (c >> 3), src + 4 * c);
                }
            }
        } else {
            for (int ci = col; ci < CI_PJ; ci += CO_PJ) {
                const float* src = xb_ + (size_t)ci * T;
                float* drow = sx + ci * PROW;
#pragma unroll
                for (int s = 0; s < (LROW + 31) / 32; ++s) {
                    int p = tx + 32 * s;
                    if (p < LROW) {
                        int g = t0 - 8 + p;
                        g = (g < 0) ? -g : (g >= T ? 2 * T - 2 - g : g);
                        cp4(drow + p + 4 * (p >> 5), src + (g - (t0 - 8)));
                    }
                }
            }
        }
        const float* wsrc = wpad + (size_t)(eoff + ji) * WFL;
        float* sw = swb + bb * WFL;
        for (int i = tid; i < WFL / 4; i += NT)
            cp16(sw + 4 * i, wsrc + 4 * i);
    };

    auto compute = [&](int bb) {
        const float* sx = smf + bb * XFL;
        const float* swp = swb + bb * WFL + col * CI_PJ * 16;
#pragma unroll
        for (int ci = 0; ci < CI_PJ; ++ci) {
            float xv[24];
            {
                const float* xrow = &sx[ci * PROW];
#pragma unroll
                for (int c = 0; c < 6; ++c) {
                    int lg = t_local + 4 * c;
                    int ph = lg + 4 * (lg >> 5);
                    ((float4*)xv)[c] = *(const float4*)(xrow + ph);
                }
            }
#pragma unroll
            for (int kc = 0; kc < 4; ++kc) {
                float4 w4 = *(const float4*)(swp + ci * 16 + 4 * kc);
                const float wa[4] = {w4.x, w4.y, w4.z, w4.w};
#pragma unroll
                for (int kk = 0; kk < 4; ++kk) {
                    const int k = 4 * kc + kk;
#pragma unroll
                    for (int tt = 0; tt < TPT; ++tt)
                        acc[tt] = fmaf(wa[kk], xv[tt + k + 1], acc[tt]);
                }
            }
        }
    };

    stage(0, 0);
    cp_commit();
    if (NBUF == 3) {
        int cur = 0;
        for (int ji = 0; ji < cnt; ++ji) {
            int nxt = (cur == 2) ? 0 : cur + 1;
            if (ji + 1 < cnt) {
                stage(nxt, ji + 1);
                cp_commit();
                cp_wait<1>();
            } else {
                cp_wait<0>();
            }
            __syncthreads();           // single barrier: tile ji visible + laggards past compute(ji-2)
            compute(cur);
            cur = nxt;
        }
    } else {
        int buf = 0;
        for (int ji = 0; ji < cnt; ++ji) {
            __syncthreads();
            if (ji + 1 < cnt) {
                stage(buf ^ 1, ji + 1);
                cp_commit();
                cp_wait<1>();
            } else {
                cp_wait<0>();
            }
            __syncthreads();
            compute(buf);
            buf ^= 1;
        }
    }

    const int cg = j * CO_PJ + col;
    const float bv = bias[cg];
    float outv[TPT];
#pragma unroll
    for (int tt = 0; tt < TPT; ++tt) {
        float v = acc[tt] + bv;
        if (LRELU) v = (v > 0.0f) ? v : 0.2f * v;
        outv[tt] = v;
    }
    const size_t obase = ((size_t)b * COUT + cg) * (size_t)T + t0 + t_local;
    if (ADD_RES) {
#pragma unroll
        for (int q = 0; q < 2; ++q) {
            float4 r4 = *(const float4*)(res + obase + 4 * q);
            outv[4 * q + 0] += r4.x; outv[4 * q + 1] += r4.y;
            outv[4 * q + 2] += r4.z; outv[4 * q + 3] += r4.w;
        }
    }
#pragma unroll
    for (int q = 0; q < 2; ++q)
        *(float4*)(y + obase + 4 * q) =
            make_float4(outv[4 * q], outv[4 * q + 1], outv[4 * q + 2], outv[4 * q + 3]);
}

// ===========================================================================
// Variant B: 2 output channels/thread, TT=256/TPT=8 (R12 exact compute).
//   NBUF semantics identical to variant A.
//   grid = (T/256, 27, BATCH), block = (32, CO_PJ/2)
// ===========================================================================
template <int CI_PJ, int CO_PJ, bool ADD_RES, bool LRELU, int MINBLK, int NBUF>
__global__ void __launch_bounds__(32 * (CO_PJ / 2), MINBLK)
sconv2_kernel(const float* __restrict__ x,
              const float* __restrict__ wpad,
              const float* __restrict__ bias,
              const float* __restrict__ res,
              float* __restrict__ y,
              int T)
{
    static_assert(CO_PJ % 2 == 0, "variant B requires even CO_PJ");
    constexpr int CIN   = CI_PJ * NJ;
    constexpr int COUT  = CO_PJ * NJ;
    constexpr int NPAIR = CO_PJ / 2;
    constexpr int TT    = 256;
    constexpr int TPT   = 8;
    constexpr int LROW  = 272;
    constexpr int PROW  = 304;
    constexpr int NT    = 32 * NPAIR;
    constexpr int NCH   = LROW / 4;
    constexpr int XFL   = CI_PJ * PROW;
    constexpr int WFL   = CO_PJ * CI_PJ * 16;

    extern __shared__ __align__(16) float smf[];
    float* swb = smf + NBUF * XFL;

    const int b   = blockIdx.z;
    const int j   = blockIdx.y;
    const int t0  = blockIdx.x * TT;
    const int tx  = threadIdx.x;
    const int pr  = threadIdx.y;
    const int tid = pr * 32 + tx;
    const int t_local = tx * TPT;
    const int co0 = 2 * pr;
    const bool boundary = (blockIdx.x == 0) | (blockIdx.x == gridDim.x - 1);

    float acc0[TPT], acc1[TPT];
#pragma unroll
    for (int i = 0; i < TPT; ++i) { acc0[i] = 0.0f; acc1[i] = 0.0f; }

    const int cnt  = c_nb_cnt[j];
    const int eoff = c_nb_off[j];

    auto stage = [&](int bb, int ji) {
        const int jn = c_nb[j][ji];
        float* sx = smf + bb * XFL;
        const float* xb_ = x + ((size_t)b * CIN + jn * CI_PJ) * (size_t)T + t0 - 8;
        if (!boundary) {
            for (int ci = pr; ci < CI_PJ; ci += NPAIR) {
                const float* src = xb_ + (size_t)ci * T;
                float* drow = sx + ci * PROW;
#pragma unroll
                for (int c0 = 0; c0 < NCH; c0 += 32) {
                    int c = c0 + tx;
                    if (c0 + 32 <= NCH || c < NCH)
                        cp16(drow + 4 * c + 4 * (c >> 3), src + 4 * c);
                }
            }
        } else {
            for (int ci = pr; ci < CI_PJ; ci += NPAIR) {
                const float* src = xb_ + (size_t)ci * T;
                float* drow = sx + ci * PROW;
#pragma unroll
                for (int s = 0; s < (LROW + 31) / 32; ++s) {
                    int p = tx + 32 * s;
                    if (p < LROW) {
                        int g = t0 - 8 + p;
                        g = (g < 0) ? -g : (g >= T ? 2 * T - 2 - g : g);
                        cp4(drow + p + 4 * (p >> 5), src + (g - (t0 - 8)));
                    }
                }
            }
        }
        const float* wsrc = wpad + (size_t)(eoff + ji) * WFL;
        float* sw = swb + bb * WFL;
        for (int i = tid; i < WFL / 4; i += NT)
            cp16(sw + 4 * i, wsrc + 4 * i);
    };

    auto compute = [&](int bb) {
        const float* sx = smf + bb * XFL;
        const float* swp0 = swb + bb * WFL + co0 * CI_PJ * 16;
        const float* swp1 = swp0 + CI_PJ * 16;
#pragma unroll
        for (int ci = 0; ci < CI_PJ; ++ci) {
            float xv[24];
            {
                const float* xrow = &sx[ci * PROW];
#pragma unroll
                for (int c = 0; c < 6; ++c) {
                    int lg = t_local + 4 * c;
                    int ph = lg + 4 * (lg >> 5);
                    ((float4*)xv)[c] = *(const float4*)(xrow + ph);
                }
            }
#pragma unroll
            for (int kc = 0; kc < 4; ++kc) {
                float4 w0 = *(const float4*)(swp0 + ci * 16 + 4 * kc);
                float4 w1 = *(const float4*)(swp1 + ci * 16 + 4 * kc);
                const float wa[4] = {w0.x, w0.y, w0.z, w0.w};
                const float wb[4] = {w1.x, w1.y, w1.z, w1.w};
#pragma unroll
                for (int kk = 0; kk < 4; ++kk) {
                    const int k = 4 * kc + kk;
#pragma unroll
                    for (int tt = 0; tt < TPT; ++tt) {
                        acc0[tt] = fmaf(wa[kk], xv[tt + k + 1], acc0[tt]);
                        acc1[tt] = fmaf(wb[kk], xv[tt + k + 1], acc1[tt]);
                    }
                }
            }
        }
    };

    stage(0, 0);
    cp_commit();
    if (NBUF == 3) {
        int cur = 0;
        for (int ji = 0; ji < cnt; ++ji) {
            int nxt = (cur == 2) ? 0 : cur + 1;
            if (ji + 1 < cnt) {
                stage(nxt, ji + 1);
                cp_commit();
                cp_wait<1>();
            } else {
                cp_wait<0>();
            }
            __syncthreads();           // single barrier per iteration
            compute(cur);
            cur = nxt;
        }
    } else {
        int buf = 0;
        for (int ji = 0; ji < cnt; ++ji) {
            __syncthreads();
            if (ji + 1 < cnt) {
                stage(buf ^ 1, ji + 1);
                cp_commit();
                cp_wait<1>();
            } else {
                cp_wait<0>();
            }
            __syncthreads();
            compute(buf);
            buf ^= 1;
        }
    }

    const int cg0 = j * CO_PJ + co0;
    const float bv0 = bias[cg0];
    const float bv1 = bias[cg0 + 1];

    float o0[TPT], o1[TPT];
#pragma unroll
    for (int tt = 0; tt < TPT; ++tt) {
        float v0 = acc0[tt] + bv0;
        float v1 = acc1[tt] + bv1;
        if (LRELU) {
            v0 = (v0 > 0.0f) ? v0 : 0.2f * v0;
            v1 = (v1 > 0.0f) ? v1 : 0.2f * v1;
        }
        o0[tt] = v0;  o1[tt] = v1;
    }
    const size_t base0 = ((size_t)b * COUT + cg0) * (size_t)T + t0 + t_local;
    if (ADD_RES) {
#pragma unroll
        for (int q = 0; q < 2; ++q) {
            float4 r4 = *(const float4*)(res + base0 + 4 * q);
            o0[4 * q + 0] += r4.x; o0[4 * q + 1] += r4.y;
            o0[4 * q + 2] += r4.z; o0[4 * q + 3] += r4.w;
        }
#pragma unroll
        for (int q = 0; q < 2; ++q) {
            float4 r4 = *(const float4*)(res + base0 + (size_t)T + 4 * q);
            o1[4 * q + 0] += r4.x; o1[4 * q + 1] += r4.y;
            o1[4 * q + 2] += r4.z; o1[4 * q + 3] += r4.w;
        }
    }
#pragma unroll
    for (int q = 0; q < 2; ++q)
        *(float4*)(y + base0 + 4 * q) =
            make_float4(o0[4 * q], o0[4 * q + 1], o0[4 * q + 2], o0[4 * q + 3]);
#pragma unroll
    for (int q = 0; q < 2; ++q)
        *(float4*)(y + base0 + (size_t)T + 4 * q) =
            make_float4(o1[4 * q], o1[4 * q + 1], o1[4 * q + 2], o1[4 * q + 3]);
}

// ---------------------------------------------------------------------------
// Elementwise sum
// ---------------------------------------------------------------------------
__global__ void add_kernel(const float* __restrict__ a, const float* __restrict__ bsrc,
                           float* __restrict__ out, int n)
{
    int i = blockIdx.x * blockDim.x + threadIdx.x;
    int i4 = 4 * i;
    if (i4 + 3 < n) {
        float4 va = *(const float4*)(a + i4);
        float4 vb = *(const float4*)(bsrc + i4);
        *(float4*)(out + i4) = make_float4(va.x + vb.x, va.y + vb.y,
                                           va.z + vb.z, va.w + vb.w);
    }
}

// ---------------------------------------------------------------------------
// Linear interp (align_corners=False) fused with noise add
// ---------------------------------------------------------------------------
__global__ void interp_add_kernel(const float* __restrict__ in,
                                  const float* __restrict__ noise,
                                  float* __restrict__ gi,
                                  float* __restrict__ sum,
                                  int Tin, int Tout, int BC)
{
    int idx = blockIdx.x * blockDim.x + threadIdx.x;
    if (idx >= BC * Tout) return;
    int t  = idx % Tout;
    int bc = idx / Tout;
    float src = ((float)t + 0.5f) * ((float)Tin / (float)Tout) - 0.5f;
    src = fminf(fmaxf(src, 0.0f), (float)(Tin - 1));
    int i0 = (int)floorf(src);
    int i1 = min(i0 + 1, Tin - 1);
    float wgt = src - (float)i0;
    const float* row = in + (size_t)bc * Tin;
    float v = row[i0] * (1.0f - wgt) + row[i1] * wgt;
    gi[idx]  = v;
    sum[idx] = v + noise[idx];
}

// ---------------------------------------------------------------------------
// Launch
// ---------------------------------------------------------------------------
static inline size_t smem_bytes(int ci_pj, int co_pj, int nbuf) {
    return (size_t)nbuf * ((size_t)ci_pj * 304 + (size_t)co_pj * ci_pj * 16) * 4u;
}

extern "C" void kernel_launch(void* const* d_in, const int* in_sizes, int n_in,
                              void* d_out, int out_size)
{
    (void)in_sizes; (void)n_in; (void)out_size;

    const float* noise0    = (const float*)d_in[0];
    const float* generated = (const float*)d_in[1];
    const float* noise1    = (const float*)d_in[2];

    const float* W[2][4];
    const float* Bv[2][4];
    int idx = 3;
    for (int s = 0; s < 2; ++s)
        for (int l = 0; l < 4; ++l) {
            W[s][l]  = (const float*)d_in[idx++];
            Bv[s][l] = (const float*)d_in[idx++];
        }

    float *bufA, *bufB, *bufC, *gi, *wpad;
    cudaGetSymbolAddress((void**)&bufA, g_bufA);
    cudaGetSymbolAddress((void**)&bufB, g_bufB);
    cudaGetSymbolAddress((void**)&bufC, g_bufC);
    cudaGetSymbolAddress((void**)&gi, g_gi);
    cudaGetSymbolAddress((void**)&wpad, g_wpad);

    float* g0 = (float*)d_out;
    float* g1 = g0 + (size_t)BATCH * 162 * T0;

    pack_all_kernel<<<(1205760 + 255) / 256, 256>>>(
        W[0][0], W[0][1], W[0][2], W[0][3],
        W[1][0], W[1][1], W[1][2], W[1][3], wpad);

    const size_t woff[2][4] = {
        {0, 75360, 200960, 452160},
        {602880, 602880 + 75360, 602880 + 200960, 602880 + 452160}
    };

    const size_t sm0 = smem_bytes(6, 5, 3);     // A, NBUF=3, single barrier
    const size_t sm1 = smem_bytes(5, 10, 3);    // B, NBUF=3, single barrier
    const size_t sm2 = smem_bytes(10, 10, 2);   // B, NBUF=2 (smem-heavy)
    const size_t sm3 = smem_bytes(10, 6, 2);    // A, NBUF=2 (smem-heavy)

    cudaFuncSetAttribute(sconv1_kernel<6, 5, false, true, 8, 3>,
                         cudaFuncAttributeMaxDynamicSharedMemorySize, (int)sm0);
    cudaFuncSetAttribute(sconv2_kernel<5, 10, false, true, 6, 3>,
                         cudaFuncAttributeMaxDynamicSharedMemorySize, (int)sm1);
    cudaFuncSetAttribute(sconv2_kernel<10, 10, false, true, 6, 2>,
                         cudaFuncAttributeMaxDynamicSharedMemorySize, (int)sm2);
    cudaFuncSetAttribute(sconv1_kernel<10, 6, true, false, 6, 2>,
                         cudaFuncAttributeMaxDynamicSharedMemorySize, (int)sm3);

    // ---------------- stage 0 (T = 4096) ----------------
    {
        int n0 = BATCH * 162 * T0;
        add_kernel<<<(n0 / 4 + 255) / 256, 256>>>(generated, noise0, bufC, n0);

        dim3 grid(T0 / 256, NJ, BATCH);
        sconv1_kernel<6, 5, false, true, 8, 3><<<grid, dim3(32, 5), sm0>>>(
            bufC, wpad + woff[0][0], Bv[0][0], nullptr, bufA, T0);
        sconv2_kernel<5, 10, false, true, 6, 3><<<grid, dim3(32, 5), sm1>>>(
            bufA, wpad + woff[0][1], Bv[0][1], nullptr, bufB, T0);
        sconv2_kernel<10, 10, false, true, 6, 2><<<grid, dim3(32, 5), sm2>>>(
            bufB, wpad + woff[0][2], Bv[0][2], nullptr, bufA, T0);
        sconv1_kernel<10, 6, true, false, 6, 2><<<grid, dim3(32, 6), sm3>>>(
            bufA, wpad + woff[0][3], Bv[0][3], generated, g0, T0);
    }

    // ---------------- upsample + noise add ----------------
    {
        int n = BATCH * 162 * T1;
        interp_add_kernel<<<(n + 255) / 256, 256>>>(g0, noise1, gi, bufC,
                                                    T0, T1, BATCH * 162);
    }

    // ---------------- stage 1 (T = 8192) ----------------
    {
        dim3 grid(T1 / 256, NJ, BATCH);
        sconv1_kernel<6, 5, false, true, 8, 3><<<grid, dim3(32, 5), sm0>>>(
            bufC, wpad + woff[1][0], Bv[1][0], nullptr, bufA, T1);
        sconv2_kernel<5, 10, false, true, 6, 3><<<grid, dim3(32, 5), sm1>>>(
            bufA, wpad + woff[1][1], Bv[1][1], nullptr, bufB, T1);
        sconv2_kernel<10, 10, false, true, 6, 2><<<grid, dim3(32, 5), sm2>>>(
            bufB, wpad + woff[1][2], Bv[1][2], nullptr, bufA, T1);
        sconv1_kernel<10, 6, true, false, 6, 2><<<grid, dim3(32, 6), sm3>>>(
            bufA, wpad + woff[1][3], Bv[1][3], gi, g1, T1);
    }
}